// round 8
// baseline (speedup 1.0000x reference)
#include <cuda_runtime.h>
#include <cuda_bf16.h>
#include <cstdint>

// ---------------------------------------------------------------------------
// HyperbolicGraphPooling: out[g] = sum_{n: batch[n]==g} sigmoid(f[n]·W+b) * f[n]
// N=500000, C=256, 2048 graphs, batch int32 sorted ascending.
// R8: dynamic chunk scheduling (32-node chunks via global atomic counter) to
// kill the inter-SM tail (DRAM idle 23% in R7), on top of the R7 cp.async
// 4-stage per-warp smem ring. Target ~79-83 us.
// ---------------------------------------------------------------------------

#define CHANNELS 256
#define THREADS  256
#define WARPS    (THREADS / 32)
#define STAGES   4
#define CHUNK    32

__device__ unsigned int g_chunk_counter;

__global__ void hgp_zero_kernel(float4* __restrict__ out, int n4) {
    int i = blockIdx.x * blockDim.x + threadIdx.x;
    if (i == 0) g_chunk_counter = 0u;           // reset work queue each replay
    if (i < n4) out[i] = make_float4(0.f, 0.f, 0.f, 0.f);
}

__device__ __forceinline__ void flush_seg(float* __restrict__ out,
                                          int seg, int num_segs, int lane,
                                          const float4& a0, const float4& a1) {
    if (seg < 0 || seg >= num_segs) return;   // defensive
    float* p0 = out + (size_t)seg * CHANNELS + 4 * lane;
    float* p1 = p0 + 128;
    atomicAdd(p0 + 0, a0.x);
    atomicAdd(p0 + 1, a0.y);
    atomicAdd(p0 + 2, a0.z);
    atomicAdd(p0 + 3, a0.w);
    atomicAdd(p1 + 0, a1.x);
    atomicAdd(p1 + 1, a1.y);
    atomicAdd(p1 + 2, a1.z);
    atomicAdd(p1 + 3, a1.w);
}

__device__ __forceinline__ void cp_row(unsigned int s_dst,
                                       const float* __restrict__ feat,
                                       int row, int lane) {
    // Each lane copies its own 32B: channels [4*lane,4*lane+4) and +128.
    const char* g = reinterpret_cast<const char*>(feat + (size_t)row * CHANNELS)
                    + lane * 16;
    asm volatile("cp.async.cg.shared.global [%0], [%1], 16;\n"
                 "cp.async.cg.shared.global [%2], [%3], 16;"
                 :: "r"(s_dst + lane * 16), "l"(g),
                    "r"(s_dst + 512 + lane * 16), "l"(g + 512));
}

__global__ __launch_bounds__(THREADS, 5)
void hgp_pool_kernel(const float* __restrict__ feat,
                     const int* __restrict__ batch,
                     const float* __restrict__ W,
                     const float* __restrict__ b,
                     float* __restrict__ out,
                     int N, int num_segs) {
    __shared__ __align__(16) float ring[WARPS][STAGES][CHANNELS];

    const int lane = threadIdx.x & 31;
    const int wid  = threadIdx.x >> 5;

    const unsigned int s_base =
        (unsigned int)__cvta_generic_to_shared(&ring[wid][0][0]);

    const float4 w0 = *reinterpret_cast<const float4*>(W + 4 * lane);
    const float4 w1 = *reinterpret_cast<const float4*>(W + 128 + 4 * lane);
    const float bias = b[0];

    for (;;) {
        // ---- grab next chunk (warp-uniform)
        unsigned int c = 0;
        if (lane == 0) c = atomicAdd(&g_chunk_counter, 1u);
        c = __shfl_sync(0xFFFFFFFFu, c, 0);
        const int n0 = (int)(c * CHUNK);
        if (n0 >= N) break;
        const int n1 = (n0 + CHUNK < N) ? n0 + CHUNK : N;

        float4 a0 = make_float4(0.f, 0.f, 0.f, 0.f);
        float4 a1 = make_float4(0.f, 0.f, 0.f, 0.f);
        int cur = __ldg(batch + n0);

        // Prologue: issue rows n0 .. n0+STAGES-2 (empty groups keep count
        // uniform; leftover groups from prior chunks are older and are also
        // drained by wait_group below).
        #pragma unroll
        for (int p = 0; p < STAGES - 1; ++p) {
            const int pn = n0 + p;
            if (pn < n1)
                cp_row(s_base + ((pn & (STAGES - 1)) << 10), feat, pn, lane);
            asm volatile("cp.async.commit_group;" ::: "memory");
        }

        for (int n = n0; n < n1; ++n) {
            const int pn = n + STAGES - 1;
            if (pn < n1)
                cp_row(s_base + ((pn & (STAGES - 1)) << 10), feat, pn, lane);
            asm volatile("cp.async.commit_group;" ::: "memory");

            const int g = __ldg(batch + n);

            // Row n's group is the 4th most recent => wait_group 3 suffices.
            asm volatile("cp.async.wait_group 3;" ::: "memory");

            // Each lane reads back exactly the 32B it wrote.
            const float* srow = &ring[wid][n & (STAGES - 1)][0];
            const float4 f0 = *reinterpret_cast<const float4*>(srow + 4 * lane);
            const float4 f1 = *reinterpret_cast<const float4*>(srow + 128 + 4 * lane);

            if (g != cur) {
                flush_seg(out, cur, num_segs, lane, a0, a1);
                a0 = make_float4(0.f, 0.f, 0.f, 0.f);
                a1 = make_float4(0.f, 0.f, 0.f, 0.f);
                cur = g;
            }

            float s = f0.x * w0.x + f0.y * w0.y + f0.z * w0.z + f0.w * w0.w
                    + f1.x * w1.x + f1.y * w1.y + f1.z * w1.z + f1.w * w1.w;
            #pragma unroll
            for (int o = 16; o > 0; o >>= 1)
                s += __shfl_xor_sync(0xFFFFFFFFu, s, o);

            const float wgt = __fdividef(1.0f, 1.0f + __expf(-(s + bias)));

            a0.x += f0.x * wgt; a0.y += f0.y * wgt;
            a0.z += f0.z * wgt; a0.w += f0.w * wgt;
            a1.x += f1.x * wgt; a1.y += f1.y * wgt;
            a1.z += f1.z * wgt; a1.w += f1.w * wgt;
        }

        flush_seg(out, cur, num_segs, lane, a0, a1);
    }
}

extern "C" void kernel_launch(void* const* d_in, const int* in_sizes, int n_in,
                              void* d_out, int out_size) {
    const float* feat  = (const float*)d_in[0];  // [N, 256] f32
    const int*   batch = (const int*)d_in[1];    // [N] i32, sorted
    const float* W     = (const float*)d_in[2];  // [256, 1] f32
    const float* b     = (const float*)d_in[3];  // [1] f32
    float*       out   = (float*)d_out;          // [num_segs, 256] f32

    const int N        = in_sizes[1];
    const int num_segs = out_size / CHANNELS;    // 2048

    const int n4 = out_size / 4;
    hgp_zero_kernel<<<(n4 + THREADS - 1) / THREADS, THREADS>>>(
        (float4*)out, n4);

    // 148 SMs * 5 blocks * 8 warps = 5920 warps pulling 32-node chunks.
    const int blocks = 740;
    hgp_pool_kernel<<<blocks, THREADS>>>(feat, batch, W, b, out, N, num_segs);
}